// round 5
// baseline (speedup 1.0000x reference)
#include <cuda_runtime.h>
#include <stdint.h>

#define NB 8
#define NANCH 13343
#define TOPK 1000
#define CAND 2048
#define NCLS 80

// ---------------- scratch (device globals; no allocation allowed) ----------------
__device__ unsigned long long g_key[NB * NANCH];   // score<<34 | (16383-a)<<7 | cls
__device__ float4             g_box4[NB * NANCH];

__device__ unsigned long long g_cand[NB * CAND];
__device__ int                g_ncand[NB];
__device__ unsigned           g_maxc_u[NB];        // order-preserving encoded float

__device__ float    g_tsc[NB * 1024];
__device__ int      g_tcl[NB * 1024];
__device__ float4   g_tbox[NB * 1024];

__device__ unsigned      g_mask[NB * TOPK * 32];
__device__ unsigned char g_rnz[NB * TOPK];

struct Ptrs {
    const float* cls[5];
    const float* cnt[5];
    const float* reg[5];
};

// order-preserving float<->unsigned encoding (monotone for all floats)
__device__ __forceinline__ unsigned enc_f(float f) {
    unsigned b = __float_as_uint(f);
    return (b & 0x80000000u) ? ~b : (b | 0x80000000u);
}
__device__ __forceinline__ float dec_f(unsigned u) {
    unsigned b = (u & 0x80000000u) ? (u ^ 0x80000000u) : ~u;
    return __uint_as_float(b);
}

// ---------------- XLA-compatible sigmoid (fma-free Horner, verified passing) ----------------
__device__ __forceinline__ float xla_tanh(float x) {
    float xc = fminf(fmaxf(x, -7.90531110763549805f), 7.90531110763549805f);
    float x2 = __fmul_rn(xc, xc);
    float p = -2.76076847742355e-16f;
    p = __fadd_rn(__fmul_rn(p, x2), 2.00018790482477e-13f);
    p = __fadd_rn(__fmul_rn(p, x2), -8.60467152213735e-11f);
    p = __fadd_rn(__fmul_rn(p, x2), 5.12229709037114e-08f);
    p = __fadd_rn(__fmul_rn(p, x2), 1.48572235717979e-05f);
    p = __fadd_rn(__fmul_rn(p, x2), 6.37261928875436e-04f);
    p = __fadd_rn(__fmul_rn(p, x2), 4.89352455891786e-03f);
    p = __fmul_rn(xc, p);
    float q = 1.19825839466702e-06f;
    q = __fadd_rn(__fmul_rn(q, x2), 1.18534705686654e-04f);
    q = __fadd_rn(__fmul_rn(q, x2), 2.26843463243900e-03f);
    q = __fadd_rn(__fmul_rn(q, x2), 4.89352518554385e-03f);
    float r = __fdiv_rn(p, q);
    return (fabsf(x) < 0.0004f) ? x : r;
}
__device__ __forceinline__ float xla_sigmoid(float x) {
    return __fadd_rn(0.5f, __fmul_rn(0.5f, xla_tanh(__fmul_rn(0.5f, x))));
}

// ---------------- kernel 1: per-anchor packed key + box ----------------
__global__ void k_score(Ptrs P) {
    int t = blockIdx.x * blockDim.x + threadIdx.x;
    if (t >= NB * NANCH) return;
    int b = t / NANCH;
    int a = t - b * NANCH;

    int l, p;
    if (a < 10000)      { l = 0; p = a; }
    else if (a < 12500) { l = 1; p = a - 10000; }
    else if (a < 13125) { l = 2; p = a - 12500; }
    else if (a < 13294) { l = 3; p = a - 13125; }
    else                { l = 4; p = a - 13294; }

    const int wlv[5] = {100, 50, 25, 13, 7};
    const int hwv[5] = {10000, 2500, 625, 169, 49};
    const int stv[5] = {8, 16, 32, 64, 128};
    int w = wlv[l], HW = hwv[l], s = stv[l];
    int y = p / w, x = p - y * w;
    float cx = (float)(x * s + (s >> 1));
    float cy = (float)(y * s + (s >> 1));

    const float* cls = P.cls[l];
    const float* cnt = P.cnt[l];
    const float* reg = P.reg[l];

    // argmax over sigmoid == argmax over logits (monotone). Track top-2 logits,
    // apply exact JAX first-occurrence semantics on their sigmoids.
    float ninf = -__int_as_float(0x7f800000);
    float m1 = ninf, m2 = ninf;
    int i1 = 0, i2 = 0;
    const float* cp = cls + (size_t)b * NCLS * HW + p;
#pragma unroll 8
    for (int c = 0; c < NCLS; c++) {
        float v = __ldg(cp + (size_t)c * HW);
        if (v > m1) { m2 = m1; i2 = i1; m1 = v; i1 = c; }
        else if (v > m2) { m2 = v; i2 = c; }
    }
    float s1 = xla_sigmoid(m1);
    float s2 = xla_sigmoid(m2);
    float best = s1;
    int bi = i1;
    if (s2 > s1 || (s2 == s1 && i2 < i1)) { best = fmaxf(s1, s2); bi = i2; }
    float cv = xla_sigmoid(__ldg(cnt + (size_t)b * HW + p));
    float score = sqrtf(__fmul_rn(best, cv));

    int o = b * NANCH + a;
    unsigned sbits = __float_as_uint(score);   // < 2^30 (score in [0,1])
    g_key[o] = ((unsigned long long)sbits << 34)
             | ((unsigned long long)(16383 - a) << 7)
             | (unsigned long long)(bi + 1);

    float r0 = __ldg(reg + ((size_t)b * 4 + 0) * HW + p);
    float r1 = __ldg(reg + ((size_t)b * 4 + 1) * HW + p);
    float r2 = __ldg(reg + ((size_t)b * 4 + 2) * HW + p);
    float r3 = __ldg(reg + ((size_t)b * 4 + 3) * HW + p);
    g_box4[o] = make_float4(__fsub_rn(cx, r0), __fsub_rn(cy, r1),
                            __fadd_rn(cx, r2), __fadd_rn(cy, r3));
}

// ---------------- kernel 2: per-batch radix-select threshold + compact candidates ----------------
__global__ __launch_bounds__(1024) void k_select() {
    __shared__ unsigned s_hist[1024];
    __shared__ unsigned s_wsum[32];
    __shared__ unsigned s_B, s_above, s_cnt;

    int b = blockIdx.x;
    int tid = threadIdx.x;
    int lane = tid & 31, wid = tid >> 5;
    const unsigned long long* kb = g_key + b * NANCH;

    if (tid == 0) g_maxc_u[b] = enc_f(-__int_as_float(0x7f800000));  // -inf

    // cache this thread's score bits in registers (14 strided slots)
    unsigned vv[14];
#pragma unroll
    for (int r = 0; r < 14; r++) {
        int i = tid + r * 1024;
        vv[r] = (i < NANCH) ? (unsigned)(kb[i] >> 34) : 0xFFFFFFFFu;  // sentinel never matches prefix
    }

    unsigned prefix = 0;
    unsigned target = TOPK;
    for (int pass = 0; pass < 3; pass++) {
        int shift = 20 - 10 * pass;
        s_hist[tid] = 0;
        __syncthreads();
#pragma unroll
        for (int r = 0; r < 14; r++) {
            unsigned v = vv[r];
            if (v != 0xFFFFFFFFu) {
                bool in = (pass == 0) || ((v >> (shift + 10)) == prefix);
                if (in) atomicAdd(&s_hist[(v >> shift) & 1023], 1u);
            }
        }
        __syncthreads();
        unsigned h = s_hist[tid];
        unsigned v = h;
#pragma unroll
        for (int off = 1; off < 32; off <<= 1) {
            unsigned u = __shfl_down_sync(0xffffffffu, v, off);
            if (lane + off < 32) v += u;
        }
        if (lane == 0) s_wsum[wid] = v;
        __syncthreads();
        if (tid < 32) {
            unsigned wv = s_wsum[tid];
            unsigned acc = wv;
#pragma unroll
            for (int off = 1; off < 32; off <<= 1) {
                unsigned u = __shfl_down_sync(0xffffffffu, acc, off);
                if (tid + off < 32) acc += u;
            }
            s_wsum[tid] = acc - wv;  // exclusive suffix of warp totals
        }
        __syncthreads();
        unsigned S = v + s_wsum[wid];
        unsigned nxt = S - h;
        if (S >= target && nxt < target) { s_B = tid; s_above = nxt; }
        __syncthreads();
        prefix = (prefix << 10) | s_B;
        target = target - s_above;
        __syncthreads();
    }
    unsigned T = prefix;  // score bits of the 1000th-largest

    if (tid == 0) s_cnt = 0;
    __syncthreads();
#pragma unroll
    for (int r = 0; r < 14; r++) {
        int i = tid + r * 1024;
        if (i < NANCH && vv[r] >= T && vv[r] != 0xFFFFFFFFu) {
            unsigned pos = atomicAdd(&s_cnt, 1u);
            if (pos < CAND) g_cand[b * CAND + pos] = kb[i];
        }
    }
    __syncthreads();
    if (tid == 0) g_ncand[b] = (int)min(s_cnt, (unsigned)CAND);
}

// ---------------- kernel 3: rank-by-count + gather into rank order ----------------
// rank(key) = #(keys > key); full-key > gives score desc, ties by smaller anchor
// (class bits sit below the anchor bits so they never affect order).
__global__ __launch_bounds__(256) void k_rankgather() {
    __shared__ unsigned long long skey[CAND];
    int b = blockIdx.y;
    int s = blockIdx.x;
    int tid = threadIdx.x;
    int n = g_ncand[b];
    if (s * 256 >= n) return;
    int n4 = (n + 3) & ~3;

    for (int i = tid; i < n4; i += 256)
        skey[i] = (i < n) ? g_cand[b * CAND + i] : 0ULL;   // 0 pad: never > any key
    __syncthreads();

    int t = s * 256 + tid;
    unsigned mu = 0;   // encoded max contribution (enc(-inf) has top bit 0 < enc(0)? use 0 = smallest)
    if (t < n) {
        unsigned long long k = skey[t];
        int cnt = 0;
        for (int j = 0; j < n4; j += 4) {
            cnt += (int)(skey[j]     > k) + (int)(skey[j + 1] > k)
                 + (int)(skey[j + 2] > k) + (int)(skey[j + 3] > k);
        }
        if (cnt < TOPK) {
            unsigned sbits = (unsigned)(k >> 34);
            int a = 16383 - (int)((k >> 7) & 16383);
            int cl = (int)(k & 127);
            float sc = __uint_as_float(sbits);
            float4 bx = g_box4[b * NANCH + a];
            int to = b * 1024 + cnt;
            g_tsc[to] = sc;
            g_tcl[to] = cl;
            g_tbox[to] = bx;
            bool valid = (sc >= 0.05f);
            float m = valid ? fmaxf(fmaxf(bx.x, bx.y), fmaxf(bx.z, bx.w)) : 0.0f;
            mu = enc_f(m);
        }
    }
    // warp-reduce encoded max, one atomic per warp
#pragma unroll
    for (int o = 16; o > 0; o >>= 1) mu = max(mu, __shfl_down_sync(0xffffffffu, mu, o));
    if ((tid & 31) == 0 && mu != 0) atomicMax(&g_maxc_u[b], mu);
}

// ---------------- kernel 4: suppression bitmask (offset/area in smem preamble) ----------------
__global__ __launch_bounds__(256) void k_mask() {
    __shared__ float sx1[TOPK], sy1[TOPK], sx2[TOPK], sy2[TOPK], sar[TOPK];
    int b = blockIdx.y;
    int tid = threadIdx.x;
    int lane = tid & 31, wrp = tid >> 5;
    int base = b * 1024;
    float maxc = dec_f(g_maxc_u[b]);

    for (int idx = tid; idx < TOPK; idx += 256) {
        float4 bx = g_tbox[base + idx];
        float off = __fmul_rn((float)g_tcl[base + idx], __fadd_rn(maxc, 1.0f));
        float ox1 = __fadd_rn(bx.x, off);
        float oy1 = __fadd_rn(bx.y, off);
        float ox2 = __fadd_rn(bx.z, off);
        float oy2 = __fadd_rn(bx.w, off);
        sx1[idx] = ox1; sy1[idx] = oy1; sx2[idx] = ox2; sy2[idx] = oy2;
        sar[idx] = __fmul_rn(__fadd_rn(__fsub_rn(ox2, ox1), 1.0f),
                             __fadd_rn(__fsub_rn(oy2, oy1), 1.0f));
    }
    __syncthreads();

    // 32 rows per block: warp wrp handles rows i0 + wrp*4 + r
    int i0 = blockIdx.x * 32;
#pragma unroll
    for (int r = 0; r < 4; r++) {
        int i = i0 + wrp * 4 + r;
        if (i >= TOPK) continue;
        float x1i = sx1[i], y1i = sy1[i], x2i = sx2[i], y2i = sy2[i], ai = sar[i];
        unsigned rowor = 0;
#pragma unroll 4
        for (int w = 0; w < 32; w++) {
            int j = w * 32 + lane;
            unsigned bit = 0;
            if (j > i && j < TOPK) {
                float xx1 = fmaxf(x1i, sx1[j]);
                float yy1 = fmaxf(y1i, sy1[j]);
                float xx2 = fminf(x2i, sx2[j]);
                float yy2 = fminf(y2i, sy2[j]);
                float iw = fmaxf(__fsub_rn(xx2, xx1), 0.0f);
                float ih = fmaxf(__fsub_rn(yy2, yy1), 0.0f);
                float inter = __fmul_rn(iw, ih);
                float uni = __fsub_rn(__fadd_rn(ai, sar[j]), inter);
                float iou = __fdiv_rn(inter, uni);
                bit = (iou > 0.6f) ? 1u : 0u;
            }
            unsigned word = __ballot_sync(0xffffffffu, bit);
            if (lane == 0) {
                g_mask[(b * TOPK + i) * 32 + w] = word;
                rowor |= word;
            }
        }
        if (lane == 0) g_rnz[b * TOPK + i] = (rowor != 0) ? 1 : 0;
    }
}

// ---------------- kernel 5: sparse greedy scan + output ----------------
__global__ __launch_bounds__(256) void k_scan(float* out) {
    __shared__ unsigned s_valid[32], s_ne[32];
    __shared__ volatile unsigned s_removed[32];

    int b = blockIdx.x;
    int tid = threadIdx.x;
    int lane = tid & 31;

    for (int k = 0; k < 4; k++) {
        int t = k * 256 + tid;
        int v = 0, nz = 0;
        if (t < TOPK) {
            v = (g_tsc[b * 1024 + t] >= 0.05f) ? 1 : 0;
            nz = g_rnz[b * TOPK + t];
        }
        unsigned bv = __ballot_sync(0xffffffffu, v);
        unsigned bn = __ballot_sync(0xffffffffu, nz);
        if (lane == 0 && t < TOPK) { s_valid[t >> 5] = bv; s_ne[t >> 5] = bn; }
    }
    if (tid < 32) s_removed[tid] = 0;
    __syncthreads();

    // warp 0: greedy scan over valid & nonempty rows, ascending (rows set bits j>i only)
    if (tid < 32) {
        for (int w = 0; w < 32; ++w) {
            unsigned cand = s_valid[w] & s_ne[w];
            while (true) {
                unsigned rm = s_removed[w];
                unsigned act = cand & ~rm;
                if (!act) break;
                int bp = __ffs(act) - 1;
                cand &= ~(1u << bp);
                int i = w * 32 + bp;
                unsigned mrow = g_mask[(b * TOPK + i) * 32 + lane];
                s_removed[lane] = s_removed[lane] | mrow;
                __syncwarp();
            }
        }
    }
    __syncthreads();

    // outputs: scores | classes | boxes
    float4* boxout = (float4*)(out + (size_t)2 * NB * TOPK);
    for (int k = 0; k < 4; k++) {
        int t = k * 256 + tid;
        if (t < TOPK) {
            unsigned rem = s_removed[t >> 5];
            bool keep = (((s_valid[t >> 5] >> (t & 31)) & 1u) != 0u) &&
                        (((rem >> (t & 31)) & 1u) == 0u);
            int to = b * 1024 + t;
            out[b * TOPK + t] = keep ? g_tsc[to] : 0.0f;
            out[NB * TOPK + b * TOPK + t] = keep ? (float)g_tcl[to] : 0.0f;
            float4 bx = g_tbox[to];
            if (!keep) bx = make_float4(0.f, 0.f, 0.f, 0.f);
            boxout[b * TOPK + t] = bx;
        }
    }
}

// ---------------- launch ----------------
extern "C" void kernel_launch(void* const* d_in, const int* in_sizes, int n_in,
                              void* d_out, int out_size) {
    (void)in_sizes; (void)n_in; (void)out_size;
    Ptrs P;
    for (int i = 0; i < 5; i++) {
        P.cls[i] = (const float*)d_in[i];
        P.cnt[i] = (const float*)d_in[5 + i];
        P.reg[i] = (const float*)d_in[10 + i];
    }
    int total = NB * NANCH;
    k_score<<<(total + 255) / 256, 256>>>(P);
    k_select<<<NB, 1024>>>();
    dim3 rg(CAND / 256, NB);
    k_rankgather<<<rg, 256>>>();
    dim3 mg((TOPK + 31) / 32, NB);
    k_mask<<<mg, 256>>>();
    k_scan<<<NB, 256>>>((float*)d_out);
}

// round 6
// speedup vs baseline: 1.5130x; 1.5130x over previous
#include <cuda_runtime.h>
#include <stdint.h>

#define NB 8
#define NANCH 13343
#define TOPK 1000
#define CAND 2048
#define NCLS 80

// ---------------- scratch (device globals; no allocation allowed) ----------------
__device__ unsigned long long g_key[NB * NANCH];   // score<<34 | (16383-a)<<7 | cls
__device__ float4             g_box4[NB * NANCH];

__device__ unsigned long long g_cand[NB * CAND];
__device__ int                g_ncand[NB];
__device__ unsigned           g_maxc_u[NB];        // order-preserving encoded float

__device__ float    g_tsc[NB * 1024];
__device__ int      g_tcl[NB * 1024];
__device__ float4   g_tbox[NB * 1024];

__device__ unsigned      g_mask[NB * TOPK * 32];
__device__ unsigned char g_rnz[NB * TOPK];

struct Ptrs {
    const float* cls[5];
    const float* cnt[5];
    const float* reg[5];
};

// order-preserving float<->unsigned encoding (monotone for all floats)
__device__ __forceinline__ unsigned enc_f(float f) {
    unsigned b = __float_as_uint(f);
    return (b & 0x80000000u) ? ~b : (b | 0x80000000u);
}
__device__ __forceinline__ float dec_f(unsigned u) {
    unsigned b = (u & 0x80000000u) ? (u ^ 0x80000000u) : ~u;
    return __uint_as_float(b);
}

// ---------------- XLA-compatible sigmoid (fma-free Horner, verified passing) ----------------
__device__ __forceinline__ float xla_tanh(float x) {
    float xc = fminf(fmaxf(x, -7.90531110763549805f), 7.90531110763549805f);
    float x2 = __fmul_rn(xc, xc);
    float p = -2.76076847742355e-16f;
    p = __fadd_rn(__fmul_rn(p, x2), 2.00018790482477e-13f);
    p = __fadd_rn(__fmul_rn(p, x2), -8.60467152213735e-11f);
    p = __fadd_rn(__fmul_rn(p, x2), 5.12229709037114e-08f);
    p = __fadd_rn(__fmul_rn(p, x2), 1.48572235717979e-05f);
    p = __fadd_rn(__fmul_rn(p, x2), 6.37261928875436e-04f);
    p = __fadd_rn(__fmul_rn(p, x2), 4.89352455891786e-03f);
    p = __fmul_rn(xc, p);
    float q = 1.19825839466702e-06f;
    q = __fadd_rn(__fmul_rn(q, x2), 1.18534705686654e-04f);
    q = __fadd_rn(__fmul_rn(q, x2), 2.26843463243900e-03f);
    q = __fadd_rn(__fmul_rn(q, x2), 4.89352518554385e-03f);
    float r = __fdiv_rn(p, q);
    return (fabsf(x) < 0.0004f) ? x : r;
}
__device__ __forceinline__ float xla_sigmoid(float x) {
    return __fadd_rn(0.5f, __fmul_rn(0.5f, xla_tanh(__fmul_rn(0.5f, x))));
}

// ---------------- kernel 1: per-anchor packed key + box ----------------
__global__ void k_score(Ptrs P) {
    int t = blockIdx.x * blockDim.x + threadIdx.x;
    if (t >= NB * NANCH) return;
    int b = t / NANCH;
    int a = t - b * NANCH;

    int l, p;
    if (a < 10000)      { l = 0; p = a; }
    else if (a < 12500) { l = 1; p = a - 10000; }
    else if (a < 13125) { l = 2; p = a - 12500; }
    else if (a < 13294) { l = 3; p = a - 13125; }
    else                { l = 4; p = a - 13294; }

    const int wlv[5] = {100, 50, 25, 13, 7};
    const int hwv[5] = {10000, 2500, 625, 169, 49};
    const int stv[5] = {8, 16, 32, 64, 128};
    int w = wlv[l], HW = hwv[l], s = stv[l];
    int y = p / w, x = p - y * w;
    float cx = (float)(x * s + (s >> 1));
    float cy = (float)(y * s + (s >> 1));

    const float* cls = P.cls[l];
    const float* cnt = P.cnt[l];
    const float* reg = P.reg[l];

    // argmax over sigmoid == argmax over logits (monotone). Track top-2 logits,
    // apply exact JAX first-occurrence semantics on their sigmoids.
    float ninf = -__int_as_float(0x7f800000);
    float m1 = ninf, m2 = ninf;
    int i1 = 0, i2 = 0;
    const float* cp = cls + (size_t)b * NCLS * HW + p;
#pragma unroll 8
    for (int c = 0; c < NCLS; c++) {
        float v = __ldg(cp + (size_t)c * HW);
        if (v > m1) { m2 = m1; i2 = i1; m1 = v; i1 = c; }
        else if (v > m2) { m2 = v; i2 = c; }
    }
    float s1 = xla_sigmoid(m1);
    float s2 = xla_sigmoid(m2);
    float best = s1;
    int bi = i1;
    if (s2 > s1 || (s2 == s1 && i2 < i1)) { best = fmaxf(s1, s2); bi = i2; }
    float cv = xla_sigmoid(__ldg(cnt + (size_t)b * HW + p));
    float score = sqrtf(__fmul_rn(best, cv));

    int o = b * NANCH + a;
    unsigned sbits = __float_as_uint(score);   // < 2^30 (score in [0,1])
    g_key[o] = ((unsigned long long)sbits << 34)
             | ((unsigned long long)(16383 - a) << 7)
             | (unsigned long long)(bi + 1);

    float r0 = __ldg(reg + ((size_t)b * 4 + 0) * HW + p);
    float r1 = __ldg(reg + ((size_t)b * 4 + 1) * HW + p);
    float r2 = __ldg(reg + ((size_t)b * 4 + 2) * HW + p);
    float r3 = __ldg(reg + ((size_t)b * 4 + 3) * HW + p);
    g_box4[o] = make_float4(__fsub_rn(cx, r0), __fsub_rn(cy, r1),
                            __fadd_rn(cx, r2), __fadd_rn(cy, r3));
}

// ---------------- kernel 2: per-batch radix-select threshold + compact candidates ----------------
__global__ __launch_bounds__(1024) void k_select() {
    __shared__ unsigned s_hist[1024];
    __shared__ unsigned s_wsum[32];
    __shared__ unsigned s_B, s_above, s_cnt;

    int b = blockIdx.x;
    int tid = threadIdx.x;
    int lane = tid & 31, wid = tid >> 5;
    const unsigned long long* kb = g_key + b * NANCH;

    if (tid == 0) g_maxc_u[b] = enc_f(-__int_as_float(0x7f800000));  // -inf

    // cache this thread's score bits in registers (14 strided slots)
    unsigned vv[14];
#pragma unroll
    for (int r = 0; r < 14; r++) {
        int i = tid + r * 1024;
        vv[r] = (i < NANCH) ? (unsigned)(kb[i] >> 34) : 0xFFFFFFFFu;  // sentinel never matches prefix
    }

    unsigned prefix = 0;
    unsigned target = TOPK;
    for (int pass = 0; pass < 3; pass++) {
        int shift = 20 - 10 * pass;
        s_hist[tid] = 0;
        __syncthreads();
#pragma unroll
        for (int r = 0; r < 14; r++) {
            unsigned v = vv[r];
            if (v != 0xFFFFFFFFu) {
                bool in = (pass == 0) || ((v >> (shift + 10)) == prefix);
                if (in) atomicAdd(&s_hist[(v >> shift) & 1023], 1u);
            }
        }
        __syncthreads();
        unsigned h = s_hist[tid];
        unsigned v = h;
#pragma unroll
        for (int off = 1; off < 32; off <<= 1) {
            unsigned u = __shfl_down_sync(0xffffffffu, v, off);
            if (lane + off < 32) v += u;
        }
        if (lane == 0) s_wsum[wid] = v;
        __syncthreads();
        if (tid < 32) {
            unsigned wv = s_wsum[tid];
            unsigned acc = wv;
#pragma unroll
            for (int off = 1; off < 32; off <<= 1) {
                unsigned u = __shfl_down_sync(0xffffffffu, acc, off);
                if (tid + off < 32) acc += u;
            }
            s_wsum[tid] = acc - wv;  // exclusive suffix of warp totals
        }
        __syncthreads();
        unsigned S = v + s_wsum[wid];
        unsigned nxt = S - h;
        if (S >= target && nxt < target) { s_B = tid; s_above = nxt; }
        __syncthreads();
        prefix = (prefix << 10) | s_B;
        target = target - s_above;
        __syncthreads();
    }
    unsigned T = prefix;  // score bits of the 1000th-largest

    if (tid == 0) s_cnt = 0;
    __syncthreads();
#pragma unroll
    for (int r = 0; r < 14; r++) {
        int i = tid + r * 1024;
        if (i < NANCH && vv[r] >= T && vv[r] != 0xFFFFFFFFu) {
            unsigned pos = atomicAdd(&s_cnt, 1u);
            if (pos < CAND) g_cand[b * CAND + pos] = kb[i];
        }
    }
    __syncthreads();
    if (tid == 0) g_ncand[b] = (int)min(s_cnt, (unsigned)CAND);
}

// ---------------- kernel 3: rank-by-count + gather into rank order ----------------
// rank(key) = #(keys > key); full-key > gives score desc, ties by smaller anchor
// (class bits sit below the anchor bits so they never affect order).
__global__ __launch_bounds__(256) void k_rankgather() {
    __shared__ unsigned long long skey[CAND];
    int b = blockIdx.y;
    int s = blockIdx.x;
    int tid = threadIdx.x;
    int n = g_ncand[b];
    if (s * 256 >= n) return;
    int n4 = (n + 3) & ~3;

    for (int i = tid; i < n4; i += 256)
        skey[i] = (i < n) ? g_cand[b * CAND + i] : 0ULL;   // 0 pad: never > any key
    __syncthreads();

    int t = s * 256 + tid;
    unsigned mu = 0;   // encoded max contribution; 0 == smallest possible
    if (t < n) {
        unsigned long long k = skey[t];
        int cnt = 0;
        for (int j = 0; j < n4; j += 4) {
            cnt += (int)(skey[j]     > k) + (int)(skey[j + 1] > k)
                 + (int)(skey[j + 2] > k) + (int)(skey[j + 3] > k);
        }
        if (cnt < TOPK) {
            unsigned sbits = (unsigned)(k >> 34);
            int a = 16383 - (int)((k >> 7) & 16383);
            int cl = (int)(k & 127);
            float sc = __uint_as_float(sbits);
            float4 bx = g_box4[b * NANCH + a];
            int to = b * 1024 + cnt;
            g_tsc[to] = sc;
            g_tcl[to] = cl;
            g_tbox[to] = bx;
            bool valid = (sc >= 0.05f);
            float m = valid ? fmaxf(fmaxf(bx.x, bx.y), fmaxf(bx.z, bx.w)) : 0.0f;
            mu = enc_f(m);
        }
    }
    // warp-reduce encoded max, one atomic per warp
#pragma unroll
    for (int o = 16; o > 0; o >>= 1) mu = max(mu, __shfl_down_sync(0xffffffffu, mu, o));
    if ((tid & 31) == 0 && mu != 0) atomicMax(&g_maxc_u[b], mu);
}

// ---------------- kernel 4: suppression bitmask (r4 shape: 1 row/warp, 1000 blocks) ----------------
__global__ __launch_bounds__(256) void k_mask() {
    __shared__ float sx1[TOPK], sy1[TOPK], sx2[TOPK], sy2[TOPK], sar[TOPK];
    int b = blockIdx.y;
    int tid = threadIdx.x;
    int lane = tid & 31, wrp = tid >> 5;
    int base = b * 1024;
    float maxc = dec_f(g_maxc_u[b]);

    for (int idx = tid; idx < TOPK; idx += 256) {
        float4 bx = g_tbox[base + idx];
        float off = __fmul_rn((float)g_tcl[base + idx], __fadd_rn(maxc, 1.0f));
        float ox1 = __fadd_rn(bx.x, off);
        float oy1 = __fadd_rn(bx.y, off);
        float ox2 = __fadd_rn(bx.z, off);
        float oy2 = __fadd_rn(bx.w, off);
        sx1[idx] = ox1; sy1[idx] = oy1; sx2[idx] = ox2; sy2[idx] = oy2;
        sar[idx] = __fmul_rn(__fadd_rn(__fsub_rn(ox2, ox1), 1.0f),
                             __fadd_rn(__fsub_rn(oy2, oy1), 1.0f));
    }
    __syncthreads();

    int i = blockIdx.x * 8 + wrp;   // 125 * 8 = 1000 rows
    if (i >= TOPK) return;
    float x1i = sx1[i], y1i = sy1[i], x2i = sx2[i], y2i = sy2[i], ai = sar[i];

    unsigned rowor = 0;
#pragma unroll 4
    for (int w = 0; w < 32; w++) {
        int j = w * 32 + lane;
        unsigned bit = 0;
        if (j > i && j < TOPK) {
            float xx1 = fmaxf(x1i, sx1[j]);
            float yy1 = fmaxf(y1i, sy1[j]);
            float xx2 = fminf(x2i, sx2[j]);
            float yy2 = fminf(y2i, sy2[j]);
            float iw = fmaxf(__fsub_rn(xx2, xx1), 0.0f);
            float ih = fmaxf(__fsub_rn(yy2, yy1), 0.0f);
            float inter = __fmul_rn(iw, ih);
            // inter==0 -> iou in {0,-0,NaN}, never > 0.6: skip the divide exactly.
            if (inter > 0.0f) {
                float uni = __fsub_rn(__fadd_rn(ai, sar[j]), inter);
                float iou = __fdiv_rn(inter, uni);
                bit = (iou > 0.6f) ? 1u : 0u;
            }
        }
        unsigned word = __ballot_sync(0xffffffffu, bit);
        if (lane == 0) {
            g_mask[(b * TOPK + i) * 32 + w] = word;
            rowor |= word;
        }
    }
    if (lane == 0) g_rnz[b * TOPK + i] = (rowor != 0) ? 1 : 0;
}

// ---------------- kernel 5: sparse greedy scan + output ----------------
__global__ __launch_bounds__(256) void k_scan(float* out) {
    __shared__ unsigned s_valid[32], s_ne[32];
    __shared__ volatile unsigned s_removed[32];

    int b = blockIdx.x;
    int tid = threadIdx.x;
    int lane = tid & 31;

    for (int k = 0; k < 4; k++) {
        int t = k * 256 + tid;
        int v = 0, nz = 0;
        if (t < TOPK) {
            v = (g_tsc[b * 1024 + t] >= 0.05f) ? 1 : 0;
            nz = g_rnz[b * TOPK + t];
        }
        unsigned bv = __ballot_sync(0xffffffffu, v);
        unsigned bn = __ballot_sync(0xffffffffu, nz);
        if (lane == 0 && t < TOPK) { s_valid[t >> 5] = bv; s_ne[t >> 5] = bn; }
    }
    if (tid < 32) s_removed[tid] = 0;
    __syncthreads();

    // warp 0: greedy scan over valid & nonempty rows, ascending (rows set bits j>i only)
    if (tid < 32) {
        for (int w = 0; w < 32; ++w) {
            unsigned cand = s_valid[w] & s_ne[w];
            while (true) {
                unsigned rm = s_removed[w];
                unsigned act = cand & ~rm;
                if (!act) break;
                int bp = __ffs(act) - 1;
                cand &= ~(1u << bp);
                int i = w * 32 + bp;
                unsigned mrow = g_mask[(b * TOPK + i) * 32 + lane];
                s_removed[lane] = s_removed[lane] | mrow;
                __syncwarp();
            }
        }
    }
    __syncthreads();

    // outputs: scores | classes | boxes
    float4* boxout = (float4*)(out + (size_t)2 * NB * TOPK);
    for (int k = 0; k < 4; k++) {
        int t = k * 256 + tid;
        if (t < TOPK) {
            unsigned rem = s_removed[t >> 5];
            bool keep = (((s_valid[t >> 5] >> (t & 31)) & 1u) != 0u) &&
                        (((rem >> (t & 31)) & 1u) == 0u);
            int to = b * 1024 + t;
            out[b * TOPK + t] = keep ? g_tsc[to] : 0.0f;
            out[NB * TOPK + b * TOPK + t] = keep ? (float)g_tcl[to] : 0.0f;
            float4 bx = g_tbox[to];
            if (!keep) bx = make_float4(0.f, 0.f, 0.f, 0.f);
            boxout[b * TOPK + t] = bx;
        }
    }
}

// ---------------- launch ----------------
extern "C" void kernel_launch(void* const* d_in, const int* in_sizes, int n_in,
                              void* d_out, int out_size) {
    (void)in_sizes; (void)n_in; (void)out_size;
    Ptrs P;
    for (int i = 0; i < 5; i++) {
        P.cls[i] = (const float*)d_in[i];
        P.cnt[i] = (const float*)d_in[5 + i];
        P.reg[i] = (const float*)d_in[10 + i];
    }
    int total = NB * NANCH;
    k_score<<<(total + 255) / 256, 256>>>(P);
    k_select<<<NB, 1024>>>();
    dim3 rg(CAND / 256, NB);
    k_rankgather<<<rg, 256>>>();
    dim3 mg(125, NB);
    k_mask<<<mg, 256>>>();
    k_scan<<<NB, 256>>>((float*)d_out);
}